// round 2
// baseline (speedup 1.0000x reference)
#include <cuda_runtime.h>

#define SEQ 8192
#define DIM 512
#define D   64
#define BM  32
#define BN  64

// Scratch for Q, K, V projections (device globals: no allocations allowed).
__device__ float g_Q[SEQ * D];
__device__ float g_K[SEQ * D];
__device__ float g_V[SEQ * D];

using u64 = unsigned long long;

// ---- packed f32x2 helpers (Blackwell FFMA2 path; ptxas only emits via PTX) ----
__device__ __forceinline__ u64 pack2(float lo, float hi) {
    u64 r; asm("mov.b64 %0, {%1, %2};" : "=l"(r) : "f"(lo), "f"(hi)); return r;
}
__device__ __forceinline__ u64 dup2(float v) { return pack2(v, v); }
__device__ __forceinline__ u64 ffma2(u64 a, u64 b, u64 c) {
    u64 d; asm("fma.rn.f32x2 %0, %1, %2, %3;" : "=l"(d) : "l"(a), "l"(b), "l"(c)); return d;
}
__device__ __forceinline__ u64 fmul2(u64 a, u64 b) {
    u64 d; asm("mul.rn.f32x2 %0, %1, %2;" : "=l"(d) : "l"(a), "l"(b)); return d;
}
__device__ __forceinline__ float2 unpack2(u64 v) {
    float lo, hi; asm("mov.b64 {%0, %1}, %2;" : "=f"(lo), "=f"(hi) : "l"(v));
    return make_float2(lo, hi);
}

// ============================================================================
// QKV projection: out[8192,64] = X[8192,512] @ W[512,64]   (grid.y selects Q/K/V)
// Q additionally pre-scaled by 1/sqrt(64) = 0.125 so attention skips the scale.
// BM=64 rows/block, full 64 cols, BK=32, 256 threads, 4x4 thread tile, FFMA2.
// ============================================================================
__global__ __launch_bounds__(256) void qkv_kernel(
    const float* __restrict__ X,
    const float* __restrict__ Wq,
    const float* __restrict__ Wk,
    const float* __restrict__ Wv)
{
    __shared__ float sX[32 * 68];  // [k][r], stride 68 floats (272B, 16B-aligned rows)
    __shared__ float sW[32 * 68];  // [k][c], stride 68

    const int m = blockIdx.y;
    const float* __restrict__ W = (m == 0) ? Wq : (m == 1) ? Wk : Wv;
    float* __restrict__ O = (m == 0) ? g_Q : (m == 1) ? g_K : g_V;

    const int row0 = blockIdx.x * 64;
    const int tid = threadIdx.x;
    const int tx = tid & 15, ty = tid >> 4;

    u64 acc[4][2];
    #pragma unroll
    for (int r = 0; r < 4; r++) { acc[r][0] = 0ull; acc[r][1] = 0ull; }

    for (int k0 = 0; k0 < DIM; k0 += 32) {
        #pragma unroll
        for (int i = tid; i < 64 * 32; i += 256) {
            int r = i >> 5, k = i & 31;
            sX[k * 68 + r] = X[(row0 + r) * DIM + k0 + k];
        }
        #pragma unroll
        for (int i = tid; i < 32 * 64; i += 256) {
            int k = i >> 6, c = i & 63;
            sW[k * 68 + c] = W[(k0 + k) * D + c];
        }
        __syncthreads();
        #pragma unroll 8
        for (int k = 0; k < 32; k++) {
            float4 a4 = *reinterpret_cast<const float4*>(&sX[k * 68 + ty * 4]);
            ulonglong2 b = *reinterpret_cast<const ulonglong2*>(&sW[k * 68 + tx * 4]);
            u64 A0 = dup2(a4.x), A1 = dup2(a4.y), A2 = dup2(a4.z), A3 = dup2(a4.w);
            acc[0][0] = ffma2(A0, b.x, acc[0][0]); acc[0][1] = ffma2(A0, b.y, acc[0][1]);
            acc[1][0] = ffma2(A1, b.x, acc[1][0]); acc[1][1] = ffma2(A1, b.y, acc[1][1]);
            acc[2][0] = ffma2(A2, b.x, acc[2][0]); acc[2][1] = ffma2(A2, b.y, acc[2][1]);
            acc[3][0] = ffma2(A3, b.x, acc[3][0]); acc[3][1] = ffma2(A3, b.y, acc[3][1]);
        }
        __syncthreads();
    }

    const float scale = (m == 0) ? 0.125f : 1.0f;
    #pragma unroll
    for (int r = 0; r < 4; r++) {
        float2 c01 = unpack2(acc[r][0]);
        float2 c23 = unpack2(acc[r][1]);
        float* o = O + (row0 + ty * 4 + r) * D + tx * 4;
        o[0] = c01.x * scale; o[1] = c01.y * scale;
        o[2] = c23.x * scale; o[3] = c23.y * scale;
    }
}

// ============================================================================
// Flash attention, fp32 with FFMA2 inner loops.
// BM=32 query rows/block (256 blocks), BN=64 keys/iter, 256 threads.
// Thread tile: 2 rows x 4 cols. Online softmax; row stats via 16-lane shuffles.
// smem: sQ [d][r] (stride 34), sK [d][c] (stride 68, aliased by sP [j][r]
// stride 34 after S is computed), sV [j][c] (stride 64).  Total 42.5 KB.
// ============================================================================
__global__ __launch_bounds__(256) void attn_kernel(float* __restrict__ out)
{
    __shared__ float sQ[D * 34];
    __shared__ float sK[D * 68];
    __shared__ float sV[BN * D];
    float* sP = sK;  // aliased: sP written only after all sK reads (sync between)

    const int tid = threadIdx.x;
    const int tx = tid & 15, ty = tid >> 4;
    const int q0 = blockIdx.x * BM;

    // Q tile, transposed [d][r] (Q already scaled by 1/8 in projection)
    #pragma unroll
    for (int i = tid; i < BM * D; i += 256) {
        int r = i >> 6, d = i & 63;
        sQ[d * 34 + r] = g_Q[(q0 + r) * D + d];
    }

    float m_old0 = -INFINITY, m_old1 = -INFINITY;
    float l0 = 0.0f, l1 = 0.0f;
    u64 o00 = 0ull, o01 = 0ull, o10 = 0ull, o11 = 0ull;

    for (int n0 = 0; n0 < SEQ; n0 += BN) {
        __syncthreads();  // previous PV finished; sK/sV/sP free (no-op at iter 0)

        #pragma unroll
        for (int i = tid; i < BN * D; i += 256) {
            int c = i >> 6, d = i & 63;
            sK[d * 68 + c] = g_K[(n0 + c) * D + d];
        }
        #pragma unroll
        for (int i = tid; i < BN * D; i += 256) {
            int j = i >> 6, c = i & 63;
            sV[j * 64 + c] = g_V[(n0 + j) * D + c];
        }
        __syncthreads();

        // ---- S = Q K^T (thread: rows 2ty+{0,1}, cols 4tx+{0..3}) ----
        u64 s00 = 0ull, s01 = 0ull, s10 = 0ull, s11 = 0ull;
        #pragma unroll 8
        for (int d = 0; d < D; d++) {
            float2 a = *reinterpret_cast<const float2*>(&sQ[d * 34 + ty * 2]);
            ulonglong2 b = *reinterpret_cast<const ulonglong2*>(&sK[d * 68 + tx * 4]);
            u64 A0 = dup2(a.x), A1 = dup2(a.y);
            s00 = ffma2(A0, b.x, s00);
            s01 = ffma2(A0, b.y, s01);
            s10 = ffma2(A1, b.x, s10);
            s11 = ffma2(A1, b.y, s11);
        }
        __syncthreads();  // all sK reads done; sP region may be overwritten

        float s[2][4];
        { float2 t;
          t = unpack2(s00); s[0][0] = t.x; s[0][1] = t.y;
          t = unpack2(s01); s[0][2] = t.x; s[0][3] = t.y;
          t = unpack2(s10); s[1][0] = t.x; s[1][1] = t.y;
          t = unpack2(s11); s[1][2] = t.x; s[1][3] = t.y; }

        // ---- online softmax ----
        float mx0 = fmaxf(fmaxf(s[0][0], s[0][1]), fmaxf(s[0][2], s[0][3]));
        float mx1 = fmaxf(fmaxf(s[1][0], s[1][1]), fmaxf(s[1][2], s[1][3]));
        #pragma unroll
        for (int off = 8; off >= 1; off >>= 1) {
            mx0 = fmaxf(mx0, __shfl_xor_sync(0xffffffffu, mx0, off));
            mx1 = fmaxf(mx1, __shfl_xor_sync(0xffffffffu, mx1, off));
        }
        float m_new0 = fmaxf(m_old0, mx0);
        float m_new1 = fmaxf(m_old1, mx1);
        float alpha0 = __expf(m_old0 - m_new0);
        float alpha1 = __expf(m_old1 - m_new1);
        m_old0 = m_new0; m_old1 = m_new1;

        float p[2][4];
        float sum0 = 0.0f, sum1 = 0.0f;
        #pragma unroll
        for (int c = 0; c < 4; c++) {
            p[0][c] = __expf(s[0][c] - m_new0); sum0 += p[0][c];
            p[1][c] = __expf(s[1][c] - m_new1); sum1 += p[1][c];
        }
        #pragma unroll
        for (int off = 8; off >= 1; off >>= 1) {
            sum0 += __shfl_xor_sync(0xffffffffu, sum0, off);
            sum1 += __shfl_xor_sync(0xffffffffu, sum1, off);
        }
        l0 = l0 * alpha0 + sum0;
        l1 = l1 * alpha1 + sum1;

        u64 A0 = dup2(alpha0), A1 = dup2(alpha1);
        o00 = fmul2(o00, A0); o01 = fmul2(o01, A0);
        o10 = fmul2(o10, A1); o11 = fmul2(o11, A1);

        // write P transposed: sP[j][r], j = 4tx+c, r = 2ty + row
        #pragma unroll
        for (int c = 0; c < 4; c++) {
            *reinterpret_cast<float2*>(&sP[(tx * 4 + c) * 34 + ty * 2]) =
                make_float2(p[0][c], p[1][c]);
        }
        __syncthreads();  // sP ready

        // ---- O += P V ----
        #pragma unroll 8
        for (int j = 0; j < BN; j++) {
            float2 a = *reinterpret_cast<const float2*>(&sP[j * 34 + ty * 2]);
            ulonglong2 b = *reinterpret_cast<const ulonglong2*>(&sV[j * 64 + tx * 4]);
            u64 P0 = dup2(a.x), P1 = dup2(a.y);
            o00 = ffma2(P0, b.x, o00);
            o01 = ffma2(P0, b.y, o01);
            o10 = ffma2(P1, b.x, o10);
            o11 = ffma2(P1, b.y, o11);
        }
    }

    // ---- epilogue: normalize and store ----
    const float inv0 = 1.0f / l0, inv1 = 1.0f / l1;
    float2 a, b;
    a = unpack2(o00); b = unpack2(o01);
    {
        float* p0 = out + (q0 + ty * 2 + 0) * D + tx * 4;
        p0[0] = a.x * inv0; p0[1] = a.y * inv0; p0[2] = b.x * inv0; p0[3] = b.y * inv0;
    }
    a = unpack2(o10); b = unpack2(o11);
    {
        float* p1 = out + (q0 + ty * 2 + 1) * D + tx * 4;
        p1[0] = a.x * inv1; p1[1] = a.y * inv1; p1[2] = b.x * inv1; p1[3] = b.y * inv1;
    }
}

extern "C" void kernel_launch(void* const* d_in, const int* in_sizes, int n_in,
                              void* d_out, int out_size) {
    (void)in_sizes; (void)n_in; (void)out_size;
    const float* X  = (const float*)d_in[0];
    const float* Wq = (const float*)d_in[1];
    const float* Wk = (const float*)d_in[2];
    const float* Wv = (const float*)d_in[3];
    float* out = (float*)d_out;

    dim3 gqkv(SEQ / 64, 3);
    qkv_kernel<<<gqkv, 256>>>(X, Wq, Wk, Wv);
    attn_kernel<<<SEQ / BM, 256>>>(out);
}

// round 3
// speedup vs baseline: 1.4494x; 1.4494x over previous
#include <cuda_runtime.h>

#define SEQ 8192
#define DIM 512
#define D   64
#define BM  64          // query rows per attn block
#define BN  128         // keys per attn iteration
#define NSPLIT 2        // KV splits

// Scratch (device globals: no allocations allowed).
__device__ float g_Qt[D * SEQ];          // Q transposed [d][row], pre-scaled by 1/8
__device__ float g_Kt[D * SEQ];          // K transposed [d][row]
__device__ float g_V [SEQ * D];          // V row-major
__device__ float g_Op[NSPLIT][SEQ * D];  // unnormalized partial O
__device__ float g_ms[NSPLIT][SEQ];      // partial row max
__device__ float g_ls[NSPLIT][SEQ];      // partial row sum

using u64 = unsigned long long;

// ---- packed f32x2 helpers (Blackwell FFMA2; ptxas only emits via PTX) ----
__device__ __forceinline__ u64 pack2(float lo, float hi) {
    u64 r; asm("mov.b64 %0, {%1, %2};" : "=l"(r) : "f"(lo), "f"(hi)); return r;
}
__device__ __forceinline__ u64 dup2(float v) { return pack2(v, v); }
__device__ __forceinline__ u64 ffma2(u64 a, u64 b, u64 c) {
    u64 d; asm("fma.rn.f32x2 %0, %1, %2, %3;" : "=l"(d) : "l"(a), "l"(b), "l"(c)); return d;
}
__device__ __forceinline__ u64 fmul2(u64 a, u64 b) {
    u64 d; asm("mul.rn.f32x2 %0, %1, %2;" : "=l"(d) : "l"(a), "l"(b)); return d;
}
__device__ __forceinline__ float2 unpack2(u64 v) {
    float lo, hi; asm("mov.b64 {%0, %1}, %2;" : "=f"(lo), "=f"(hi) : "l"(v));
    return make_float2(lo, hi);
}

// ============================================================================
// QKV projection: [8192,512] @ [512,64]. grid.y: 0=Q(->g_Qt, scaled 1/8),
// 1=K(->g_Kt), 2=V(->g_V row-major). 64 rows/block, 256 thr, 4x4 tile, FFMA2.
// ============================================================================
__global__ __launch_bounds__(256) void qkv_kernel(
    const float* __restrict__ X,
    const float* __restrict__ Wq,
    const float* __restrict__ Wk,
    const float* __restrict__ Wv)
{
    __shared__ float sX[32 * 68];  // [k][r]
    __shared__ float sW[32 * 68];  // [k][c]

    const int m = blockIdx.y;
    const float* __restrict__ W = (m == 0) ? Wq : (m == 1) ? Wk : Wv;

    const int row0 = blockIdx.x * 64;
    const int tid = threadIdx.x;
    const int tx = tid & 15, ty = tid >> 4;

    u64 acc[4][2];
    #pragma unroll
    for (int r = 0; r < 4; r++) { acc[r][0] = 0ull; acc[r][1] = 0ull; }

    for (int k0 = 0; k0 < DIM; k0 += 32) {
        #pragma unroll
        for (int i = tid; i < 64 * 32; i += 256) {
            int r = i >> 5, k = i & 31;
            sX[k * 68 + r] = X[(row0 + r) * DIM + k0 + k];
        }
        #pragma unroll
        for (int i = tid; i < 32 * 64; i += 256) {
            int k = i >> 6, c = i & 63;
            sW[k * 68 + c] = W[(k0 + k) * D + c];
        }
        __syncthreads();
        #pragma unroll 8
        for (int k = 0; k < 32; k++) {
            float4 a4 = *reinterpret_cast<const float4*>(&sX[k * 68 + ty * 4]);
            ulonglong2 b = *reinterpret_cast<const ulonglong2*>(&sW[k * 68 + tx * 4]);
            u64 A0 = dup2(a4.x), A1 = dup2(a4.y), A2 = dup2(a4.z), A3 = dup2(a4.w);
            acc[0][0] = ffma2(A0, b.x, acc[0][0]); acc[0][1] = ffma2(A0, b.y, acc[0][1]);
            acc[1][0] = ffma2(A1, b.x, acc[1][0]); acc[1][1] = ffma2(A1, b.y, acc[1][1]);
            acc[2][0] = ffma2(A2, b.x, acc[2][0]); acc[2][1] = ffma2(A2, b.y, acc[2][1]);
            acc[3][0] = ffma2(A3, b.x, acc[3][0]); acc[3][1] = ffma2(A3, b.y, acc[3][1]);
        }
        __syncthreads();
    }

    float f[4][4];
    #pragma unroll
    for (int r = 0; r < 4; r++) {
        float2 c01 = unpack2(acc[r][0]);
        float2 c23 = unpack2(acc[r][1]);
        f[r][0] = c01.x; f[r][1] = c01.y; f[r][2] = c23.x; f[r][3] = c23.y;
    }

    if (m == 2) {
        // V: row-major
        #pragma unroll
        for (int r = 0; r < 4; r++) {
            float* o = g_V + (row0 + ty * 4 + r) * D + tx * 4;
            *reinterpret_cast<float4*>(o) = make_float4(f[r][0], f[r][1], f[r][2], f[r][3]);
        }
    } else {
        // Q/K: transposed [col][row]; Q scaled by 1/8
        const float scale = (m == 0) ? 0.125f : 1.0f;
        float* __restrict__ T = (m == 0) ? g_Qt : g_Kt;
        #pragma unroll
        for (int cc = 0; cc < 4; cc++) {
            int col = tx * 4 + cc;
            *reinterpret_cast<float4*>(&T[col * SEQ + row0 + ty * 4]) =
                make_float4(f[0][cc] * scale, f[1][cc] * scale,
                            f[2][cc] * scale, f[3][cc] * scale);
        }
    }
}

// ============================================================================
// Flash attention, fp32 FFMA2. BM=64 rows/block, BN=128 keys/iter, KV split 2.
// 256 threads = 16 tx (8 cols each over BN; 4 cols each over D) x 16 ty (4 rows).
// Dyn smem: sQ [64][68] | sK [64][136] (aliased by sP [128][68]) | sV [128][64].
// ============================================================================
#define SQ_STR 68
#define SK_STR 136
#define SP_STR 68
#define SV_STR 64
#define SMEM_Q   (D * SQ_STR)                 // 4352
#define SMEM_KP  (D * SK_STR)                 // 8704 (== 128*68 for sP)
#define SMEM_V   (BN * SV_STR)                // 8192
#define ATTN_SMEM_BYTES ((SMEM_Q + SMEM_KP + SMEM_V) * 4)   // 84992

__global__ __launch_bounds__(256, 2) void attn_kernel()
{
    extern __shared__ float sm[];
    float* sQ = sm;
    float* sK = sm + SMEM_Q;
    float* sP = sK;                  // alias; barriers separate uses
    float* sV = sm + SMEM_Q + SMEM_KP;

    const int tid = threadIdx.x;
    const int tx = tid & 15, ty = tid >> 4;
    const int q0 = blockIdx.x * BM;
    const int split = blockIdx.y;
    const int n_begin = split * (SEQ / NSPLIT);
    const int n_end = n_begin + SEQ / NSPLIT;

    // Q tile [d][r] from g_Qt (coalesced, contiguous STS)
    #pragma unroll
    for (int i = tid; i < BM * D / 4; i += 256) {
        int d = i >> 4, r4 = (i & 15) * 4;
        float4 v = *reinterpret_cast<const float4*>(&g_Qt[d * SEQ + q0 + r4]);
        *reinterpret_cast<float4*>(&sQ[d * SQ_STR + r4]) = v;
    }

    float m_[4], l_[4];
    u64 accO[4][2];
    #pragma unroll
    for (int r = 0; r < 4; r++) {
        m_[r] = -INFINITY; l_[r] = 0.0f;
        accO[r][0] = 0ull; accO[r][1] = 0ull;
    }

    const int xoff = (ty * 4) ^ ((tx & 7) * 8);   // P-store swizzle

    for (int n0 = n_begin; n0 < n_end; n0 += BN) {
        __syncthreads();   // prev PV done: sP(sK)/sV reusable

        // K^T tile: sK[d][c] = Kt[d][n0+c]  (coalesced, contiguous)
        #pragma unroll
        for (int i = tid; i < D * BN / 4; i += 256) {
            int d = i >> 5, c4 = (i & 31) * 4;
            float4 v = *reinterpret_cast<const float4*>(&g_Kt[d * SEQ + n0 + c4]);
            *reinterpret_cast<float4*>(&sK[d * SK_STR + c4]) = v;
        }
        // V tile: sV[j][dv]
        #pragma unroll
        for (int i = tid; i < BN * D / 4; i += 256) {
            int j = i >> 4, d4 = (i & 15) * 4;
            float4 v = *reinterpret_cast<const float4*>(&g_V[(n0 + j) * D + d4]);
            *reinterpret_cast<float4*>(&sV[j * SV_STR + d4]) = v;
        }
        __syncthreads();

        // ---- S = Q K^T : per-thread 4 rows x 8 cols ----
        u64 acc[4][4];
        #pragma unroll
        for (int r = 0; r < 4; r++)
            #pragma unroll
            for (int c = 0; c < 4; c++) acc[r][c] = 0ull;

        #pragma unroll 8
        for (int d = 0; d < D; d++) {
            float4 q = *reinterpret_cast<const float4*>(&sQ[d * SQ_STR + ty * 4]);
            ulonglong2 ka = *reinterpret_cast<const ulonglong2*>(&sK[d * SK_STR + tx * 8]);
            ulonglong2 kb = *reinterpret_cast<const ulonglong2*>(&sK[d * SK_STR + tx * 8 + 4]);
            u64 A0 = dup2(q.x), A1 = dup2(q.y), A2 = dup2(q.z), A3 = dup2(q.w);
            acc[0][0] = ffma2(A0, ka.x, acc[0][0]); acc[0][1] = ffma2(A0, ka.y, acc[0][1]);
            acc[0][2] = ffma2(A0, kb.x, acc[0][2]); acc[0][3] = ffma2(A0, kb.y, acc[0][3]);
            acc[1][0] = ffma2(A1, ka.x, acc[1][0]); acc[1][1] = ffma2(A1, ka.y, acc[1][1]);
            acc[1][2] = ffma2(A1, kb.x, acc[1][2]); acc[1][3] = ffma2(A1, kb.y, acc[1][3]);
            acc[2][0] = ffma2(A2, ka.x, acc[2][0]); acc[2][1] = ffma2(A2, ka.y, acc[2][1]);
            acc[2][2] = ffma2(A2, kb.x, acc[2][2]); acc[2][3] = ffma2(A2, kb.y, acc[2][3]);
            acc[3][0] = ffma2(A3, ka.x, acc[3][0]); acc[3][1] = ffma2(A3, ka.y, acc[3][1]);
            acc[3][2] = ffma2(A3, kb.x, acc[3][2]); acc[3][3] = ffma2(A3, kb.y, acc[3][3]);
        }
        __syncthreads();   // sK reads complete; sP region free

        // ---- online softmax (rows reduced across 16 tx lanes) ----
        float s[4][8];
        #pragma unroll
        for (int r = 0; r < 4; r++) {
            #pragma unroll
            for (int c = 0; c < 4; c++) {
                float2 t = unpack2(acc[r][c]);
                s[r][2 * c] = t.x; s[r][2 * c + 1] = t.y;
            }
        }
        #pragma unroll
        for (int r = 0; r < 4; r++) {
            float mx = s[r][0];
            #pragma unroll
            for (int c = 1; c < 8; c++) mx = fmaxf(mx, s[r][c]);
            #pragma unroll
            for (int off = 8; off >= 1; off >>= 1)
                mx = fmaxf(mx, __shfl_xor_sync(0xffffffffu, mx, off));
            float mn = fmaxf(m_[r], mx);
            float alpha = __expf(m_[r] - mn);
            m_[r] = mn;
            float sum = 0.0f;
            #pragma unroll
            for (int c = 0; c < 8; c++) {
                float p = __expf(s[r][c] - mn);
                s[r][c] = p;
                sum += p;
            }
            #pragma unroll
            for (int off = 8; off >= 1; off >>= 1)
                sum += __shfl_xor_sync(0xffffffffu, sum, off);
            l_[r] = l_[r] * alpha + sum;
            u64 A = dup2(alpha);
            accO[r][0] = fmul2(accO[r][0], A);
            accO[r][1] = fmul2(accO[r][1], A);
        }

        // write P (transposed [j][r], XOR-swizzled base to dodge bank conflicts)
        #pragma unroll
        for (int c = 0; c < 8; c++) {
            *reinterpret_cast<float4*>(&sP[(tx * 8 + c) * SP_STR + xoff]) =
                make_float4(s[0][c], s[1][c], s[2][c], s[3][c]);
        }
        __syncthreads();   // sP ready

        // ---- O += P V : per-thread 4 rows x 4 output cols ----
        #pragma unroll 2
        for (int jo = 0; jo < BN / 8; jo++) {
            const int xo = (ty * 4) ^ ((jo & 7) * 8);
            #pragma unroll
            for (int jc = 0; jc < 8; jc++) {
                int j = jo * 8 + jc;
                float4 p = *reinterpret_cast<const float4*>(&sP[j * SP_STR + xo]);
                ulonglong2 v = *reinterpret_cast<const ulonglong2*>(&sV[j * SV_STR + tx * 4]);
                u64 P0 = dup2(p.x), P1 = dup2(p.y), P2 = dup2(p.z), P3 = dup2(p.w);
                accO[0][0] = ffma2(P0, v.x, accO[0][0]); accO[0][1] = ffma2(P0, v.y, accO[0][1]);
                accO[1][0] = ffma2(P1, v.x, accO[1][0]); accO[1][1] = ffma2(P1, v.y, accO[1][1]);
                accO[2][0] = ffma2(P2, v.x, accO[2][0]); accO[2][1] = ffma2(P2, v.y, accO[2][1]);
                accO[3][0] = ffma2(P3, v.x, accO[3][0]); accO[3][1] = ffma2(P3, v.y, accO[3][1]);
            }
        }
    }

    // ---- epilogue: write unnormalized partials + stats ----
    #pragma unroll
    for (int r = 0; r < 4; r++) {
        int row = q0 + ty * 4 + r;
        if (tx == 0) { g_ms[0][0] = g_ms[0][0]; }  // no-op to keep structure simple
        float2 a = unpack2(accO[r][0]);
        float2 b = unpack2(accO[r][1]);
        *reinterpret_cast<float4*>(&g_Op[split][row * D + tx * 4]) =
            make_float4(a.x, a.y, b.x, b.y);
        if (tx == 0) {
            g_ms[split][row] = m_[r];
            g_ls[split][row] = l_[r];
        }
    }
}

// ============================================================================
// Merge the NSPLIT partials:  out = sum_i e^{m_i-m} O_i / sum_i e^{m_i-m} l_i
// ============================================================================
__global__ __launch_bounds__(256) void merge_kernel(float* __restrict__ out)
{
    int idx = blockIdx.x * 256 + threadIdx.x;   // over SEQ*D
    int row = idx >> 6;
    float m0 = g_ms[0][row], m1 = g_ms[1][row];
    float m = fmaxf(m0, m1);
    float e0 = __expf(m0 - m), e1 = __expf(m1 - m);
    float denom = e0 * g_ls[0][row] + e1 * g_ls[1][row];
    out[idx] = (e0 * g_Op[0][idx] + e1 * g_Op[1][idx]) / denom;
}

extern "C" void kernel_launch(void* const* d_in, const int* in_sizes, int n_in,
                              void* d_out, int out_size) {
    (void)in_sizes; (void)n_in; (void)out_size;
    const float* X  = (const float*)d_in[0];
    const float* Wq = (const float*)d_in[1];
    const float* Wk = (const float*)d_in[2];
    const float* Wv = (const float*)d_in[3];
    float* out = (float*)d_out;

    cudaFuncSetAttribute(attn_kernel,
                         cudaFuncAttributeMaxDynamicSharedMemorySize,
                         ATTN_SMEM_BYTES);

    dim3 gqkv(SEQ / 64, 3);
    qkv_kernel<<<gqkv, 256>>>(X, Wq, Wk, Wv);

    dim3 gattn(SEQ / BM, NSPLIT);
    attn_kernel<<<gattn, 256, ATTN_SMEM_BYTES>>>();

    merge_kernel<<<SEQ * D / 256, 256>>>(out);
}

// round 5
// speedup vs baseline: 1.4508x; 1.0010x over previous
#include <cuda_runtime.h>

#define SEQ 8192
#define DIM 512
#define D   64
#define BM  64          // query rows per attn block
#define BN  128         // keys per attn iteration
#define NSPLIT 2        // KV splits

// Scratch (device globals: no allocations allowed).
__device__ float g_Qt[D * SEQ];          // Q transposed [d][row], pre-scaled by 1/8
__device__ float g_Kt[D * SEQ];          // K transposed [d][row]
__device__ float g_V [SEQ * D];          // V row-major
__device__ float g_Op[NSPLIT][SEQ * D];  // unnormalized partial O
__device__ float g_ms[NSPLIT][SEQ];      // partial row max
__device__ float g_ls[NSPLIT][SEQ];      // partial row sum

using u64 = unsigned long long;

// ---- packed f32x2 helpers (Blackwell FFMA2; ptxas only emits via PTX) ----
__device__ __forceinline__ u64 pack2(float lo, float hi) {
    u64 r; asm("mov.b64 %0, {%1, %2};" : "=l"(r) : "f"(lo), "f"(hi)); return r;
}
__device__ __forceinline__ u64 dup2(float v) { return pack2(v, v); }
__device__ __forceinline__ u64 ffma2(u64 a, u64 b, u64 c) {
    u64 d; asm("fma.rn.f32x2 %0, %1, %2, %3;" : "=l"(d) : "l"(a), "l"(b), "l"(c)); return d;
}
__device__ __forceinline__ u64 fmul2(u64 a, u64 b) {
    u64 d; asm("mul.rn.f32x2 %0, %1, %2;" : "=l"(d) : "l"(a), "l"(b)); return d;
}
__device__ __forceinline__ float2 unpack2(u64 v) {
    float lo, hi; asm("mov.b64 {%0, %1}, %2;" : "=f"(lo), "=f"(hi) : "l"(v));
    return make_float2(lo, hi);
}

// ============================================================================
// QKV projection: [8192,512] @ [512,64]. grid.y: 0=Q(->g_Qt, scaled 1/8),
// 1=K(->g_Kt), 2=V(->g_V row-major). 64 rows/block, 256 thr, 4x4 tile, FFMA2.
// ============================================================================
__global__ __launch_bounds__(256) void qkv_kernel(
    const float* __restrict__ X,
    const float* __restrict__ Wq,
    const float* __restrict__ Wk,
    const float* __restrict__ Wv)
{
    __shared__ float sX[32 * 68];  // [k][r]
    __shared__ float sW[32 * 68];  // [k][c]

    const int m = blockIdx.y;
    const float* __restrict__ W = (m == 0) ? Wq : (m == 1) ? Wk : Wv;

    const int row0 = blockIdx.x * 64;
    const int tid = threadIdx.x;
    const int tx = tid & 15, ty = tid >> 4;

    u64 acc[4][2];
    #pragma unroll
    for (int r = 0; r < 4; r++) { acc[r][0] = 0ull; acc[r][1] = 0ull; }

    for (int k0 = 0; k0 < DIM; k0 += 32) {
        #pragma unroll
        for (int i = tid; i < 64 * 32; i += 256) {
            int r = i >> 5, k = i & 31;
            sX[k * 68 + r] = X[(row0 + r) * DIM + k0 + k];
        }
        #pragma unroll
        for (int i = tid; i < 32 * 64; i += 256) {
            int k = i >> 6, c = i & 63;
            sW[k * 68 + c] = W[(k0 + k) * D + c];
        }
        __syncthreads();
        #pragma unroll 8
        for (int k = 0; k < 32; k++) {
            float4 a4 = *reinterpret_cast<const float4*>(&sX[k * 68 + ty * 4]);
            ulonglong2 b = *reinterpret_cast<const ulonglong2*>(&sW[k * 68 + tx * 4]);
            u64 A0 = dup2(a4.x), A1 = dup2(a4.y), A2 = dup2(a4.z), A3 = dup2(a4.w);
            acc[0][0] = ffma2(A0, b.x, acc[0][0]); acc[0][1] = ffma2(A0, b.y, acc[0][1]);
            acc[1][0] = ffma2(A1, b.x, acc[1][0]); acc[1][1] = ffma2(A1, b.y, acc[1][1]);
            acc[2][0] = ffma2(A2, b.x, acc[2][0]); acc[2][1] = ffma2(A2, b.y, acc[2][1]);
            acc[3][0] = ffma2(A3, b.x, acc[3][0]); acc[3][1] = ffma2(A3, b.y, acc[3][1]);
        }
        __syncthreads();
    }

    float f[4][4];
    #pragma unroll
    for (int r = 0; r < 4; r++) {
        float2 c01 = unpack2(acc[r][0]);
        float2 c23 = unpack2(acc[r][1]);
        f[r][0] = c01.x; f[r][1] = c01.y; f[r][2] = c23.x; f[r][3] = c23.y;
    }

    if (m == 2) {
        // V: row-major
        #pragma unroll
        for (int r = 0; r < 4; r++) {
            float* o = g_V + (row0 + ty * 4 + r) * D + tx * 4;
            *reinterpret_cast<float4*>(o) = make_float4(f[r][0], f[r][1], f[r][2], f[r][3]);
        }
    } else {
        // Q/K: transposed [col][row]; Q scaled by 1/8
        const float scale = (m == 0) ? 0.125f : 1.0f;
        float* __restrict__ T = (m == 0) ? g_Qt : g_Kt;
        #pragma unroll
        for (int cc = 0; cc < 4; cc++) {
            int col = tx * 4 + cc;
            *reinterpret_cast<float4*>(&T[col * SEQ + row0 + ty * 4]) =
                make_float4(f[0][cc] * scale, f[1][cc] * scale,
                            f[2][cc] * scale, f[3][cc] * scale);
        }
    }
}

// ============================================================================
// Flash attention, fp32 FFMA2. BM=64 rows/block, BN=128 keys/iter, KV split 2.
// 256 threads = 16 tx (8 cols each over BN; 4 cols each over D) x 16 ty (4 rows).
// Dyn smem: sQ [64][68] | sK [64][136] (aliased by sP [128][68]) | sV [128][64].
// ============================================================================
#define SQ_STR 68
#define SK_STR 136
#define SP_STR 68
#define SV_STR 64
#define SMEM_Q   (D * SQ_STR)                 // 4352
#define SMEM_KP  (D * SK_STR)                 // 8704 (== 128*68 for sP)
#define SMEM_V   (BN * SV_STR)                // 8192
#define ATTN_SMEM_BYTES ((SMEM_Q + SMEM_KP + SMEM_V) * 4)   // 84992

__global__ __launch_bounds__(256, 2) void attn_kernel()
{
    extern __shared__ float sm[];
    float* sQ = sm;
    float* sK = sm + SMEM_Q;
    float* sP = sK;                  // alias; barriers separate uses
    float* sV = sm + SMEM_Q + SMEM_KP;

    const int tid = threadIdx.x;
    const int tx = tid & 15, ty = tid >> 4;
    const int q0 = blockIdx.x * BM;
    const int split = blockIdx.y;
    const int n_begin = split * (SEQ / NSPLIT);
    const int n_end = n_begin + SEQ / NSPLIT;

    // Q tile [d][r] from g_Qt (coalesced, contiguous STS)
    #pragma unroll
    for (int i = tid; i < BM * D / 4; i += 256) {
        int d = i >> 4, r4 = (i & 15) * 4;
        float4 v = *reinterpret_cast<const float4*>(&g_Qt[d * SEQ + q0 + r4]);
        *reinterpret_cast<float4*>(&sQ[d * SQ_STR + r4]) = v;
    }

    float m_[4], l_[4];
    u64 accO[4][2];
    #pragma unroll
    for (int r = 0; r < 4; r++) {
        m_[r] = -INFINITY; l_[r] = 0.0f;
        accO[r][0] = 0ull; accO[r][1] = 0ull;
    }

    const int xoff = (ty * 4) ^ ((tx & 7) * 8);   // P-store swizzle

    for (int n0 = n_begin; n0 < n_end; n0 += BN) {
        __syncthreads();   // prev PV done: sP(sK)/sV reusable

        // K^T tile: sK[d][c] = Kt[d][n0+c]  (coalesced, contiguous)
        #pragma unroll
        for (int i = tid; i < D * BN / 4; i += 256) {
            int d = i >> 5, c4 = (i & 31) * 4;
            float4 v = *reinterpret_cast<const float4*>(&g_Kt[d * SEQ + n0 + c4]);
            *reinterpret_cast<float4*>(&sK[d * SK_STR + c4]) = v;
        }
        // V tile: sV[j][dv]
        #pragma unroll
        for (int i = tid; i < BN * D / 4; i += 256) {
            int j = i >> 4, d4 = (i & 15) * 4;
            float4 v = *reinterpret_cast<const float4*>(&g_V[(n0 + j) * D + d4]);
            *reinterpret_cast<float4*>(&sV[j * SV_STR + d4]) = v;
        }
        __syncthreads();

        // ---- S = Q K^T : per-thread 4 rows x 8 cols ----
        u64 acc[4][4];
        #pragma unroll
        for (int r = 0; r < 4; r++)
            #pragma unroll
            for (int c = 0; c < 4; c++) acc[r][c] = 0ull;

        #pragma unroll 8
        for (int d = 0; d < D; d++) {
            float4 q = *reinterpret_cast<const float4*>(&sQ[d * SQ_STR + ty * 4]);
            ulonglong2 ka = *reinterpret_cast<const ulonglong2*>(&sK[d * SK_STR + tx * 8]);
            ulonglong2 kb = *reinterpret_cast<const ulonglong2*>(&sK[d * SK_STR + tx * 8 + 4]);
            u64 A0 = dup2(q.x), A1 = dup2(q.y), A2 = dup2(q.z), A3 = dup2(q.w);
            acc[0][0] = ffma2(A0, ka.x, acc[0][0]); acc[0][1] = ffma2(A0, ka.y, acc[0][1]);
            acc[0][2] = ffma2(A0, kb.x, acc[0][2]); acc[0][3] = ffma2(A0, kb.y, acc[0][3]);
            acc[1][0] = ffma2(A1, ka.x, acc[1][0]); acc[1][1] = ffma2(A1, ka.y, acc[1][1]);
            acc[1][2] = ffma2(A1, kb.x, acc[1][2]); acc[1][3] = ffma2(A1, kb.y, acc[1][3]);
            acc[2][0] = ffma2(A2, ka.x, acc[2][0]); acc[2][1] = ffma2(A2, ka.y, acc[2][1]);
            acc[2][2] = ffma2(A2, kb.x, acc[2][2]); acc[2][3] = ffma2(A2, kb.y, acc[2][3]);
            acc[3][0] = ffma2(A3, ka.x, acc[3][0]); acc[3][1] = ffma2(A3, ka.y, acc[3][1]);
            acc[3][2] = ffma2(A3, kb.x, acc[3][2]); acc[3][3] = ffma2(A3, kb.y, acc[3][3]);
        }
        __syncthreads();   // sK reads complete; sP region free

        // ---- online softmax (rows reduced across 16 tx lanes) ----
        float s[4][8];
        #pragma unroll
        for (int r = 0; r < 4; r++) {
            #pragma unroll
            for (int c = 0; c < 4; c++) {
                float2 t = unpack2(acc[r][c]);
                s[r][2 * c] = t.x; s[r][2 * c + 1] = t.y;
            }
        }
        #pragma unroll
        for (int r = 0; r < 4; r++) {
            float mx = s[r][0];
            #pragma unroll
            for (int c = 1; c < 8; c++) mx = fmaxf(mx, s[r][c]);
            #pragma unroll
            for (int off = 8; off >= 1; off >>= 1)
                mx = fmaxf(mx, __shfl_xor_sync(0xffffffffu, mx, off));
            float mn = fmaxf(m_[r], mx);
            float alpha = __expf(m_[r] - mn);
            m_[r] = mn;
            float sum = 0.0f;
            #pragma unroll
            for (int c = 0; c < 8; c++) {
                float p = __expf(s[r][c] - mn);
                s[r][c] = p;
                sum += p;
            }
            #pragma unroll
            for (int off = 8; off >= 1; off >>= 1)
                sum += __shfl_xor_sync(0xffffffffu, sum, off);
            l_[r] = l_[r] * alpha + sum;
            u64 A = dup2(alpha);
            accO[r][0] = fmul2(accO[r][0], A);
            accO[r][1] = fmul2(accO[r][1], A);
        }

        // write P (transposed [j][r], XOR-swizzled base to dodge bank conflicts)
        #pragma unroll
        for (int c = 0; c < 8; c++) {
            *reinterpret_cast<float4*>(&sP[(tx * 8 + c) * SP_STR + xoff]) =
                make_float4(s[0][c], s[1][c], s[2][c], s[3][c]);
        }
        __syncthreads();   // sP ready

        // ---- O += P V : per-thread 4 rows x 4 output cols ----
        #pragma unroll 2
        for (int jo = 0; jo < BN / 8; jo++) {
            const int xo = (ty * 4) ^ ((jo & 7) * 8);
            #pragma unroll
            for (int jc = 0; jc < 8; jc++) {
                int j = jo * 8 + jc;
                float4 p = *reinterpret_cast<const float4*>(&sP[j * SP_STR + xo]);
                ulonglong2 v = *reinterpret_cast<const ulonglong2*>(&sV[j * SV_STR + tx * 4]);
                u64 P0 = dup2(p.x), P1 = dup2(p.y), P2 = dup2(p.z), P3 = dup2(p.w);
                accO[0][0] = ffma2(P0, v.x, accO[0][0]); accO[0][1] = ffma2(P0, v.y, accO[0][1]);
                accO[1][0] = ffma2(P1, v.x, accO[1][0]); accO[1][1] = ffma2(P1, v.y, accO[1][1]);
                accO[2][0] = ffma2(P2, v.x, accO[2][0]); accO[2][1] = ffma2(P2, v.y, accO[2][1]);
                accO[3][0] = ffma2(P3, v.x, accO[3][0]); accO[3][1] = ffma2(P3, v.y, accO[3][1]);
            }
        }
    }

    // ---- epilogue: write unnormalized partials + stats ----
    #pragma unroll
    for (int r = 0; r < 4; r++) {
        int row = q0 + ty * 4 + r;
        if (tx == 0) { g_ms[0][0] = g_ms[0][0]; }  // no-op to keep structure simple
        float2 a = unpack2(accO[r][0]);
        float2 b = unpack2(accO[r][1]);
        *reinterpret_cast<float4*>(&g_Op[split][row * D + tx * 4]) =
            make_float4(a.x, a.y, b.x, b.y);
        if (tx == 0) {
            g_ms[split][row] = m_[r];
            g_ls[split][row] = l_[r];
        }
    }
}

// ============================================================================
// Merge the NSPLIT partials:  out = sum_i e^{m_i-m} O_i / sum_i e^{m_i-m} l_i
// ============================================================================
__global__ __launch_bounds__(256) void merge_kernel(float* __restrict__ out)
{
    int idx = blockIdx.x * 256 + threadIdx.x;   // over SEQ*D
    int row = idx >> 6;
    float m0 = g_ms[0][row], m1 = g_ms[1][row];
    float m = fmaxf(m0, m1);
    float e0 = __expf(m0 - m), e1 = __expf(m1 - m);
    float denom = e0 * g_ls[0][row] + e1 * g_ls[1][row];
    out[idx] = (e0 * g_Op[0][idx] + e1 * g_Op[1][idx]) / denom;
}

extern "C" void kernel_launch(void* const* d_in, const int* in_sizes, int n_in,
                              void* d_out, int out_size) {
    (void)in_sizes; (void)n_in; (void)out_size;
    const float* X  = (const float*)d_in[0];
    const float* Wq = (const float*)d_in[1];
    const float* Wk = (const float*)d_in[2];
    const float* Wv = (const float*)d_in[3];
    float* out = (float*)d_out;

    cudaFuncSetAttribute(attn_kernel,
                         cudaFuncAttributeMaxDynamicSharedMemorySize,
                         ATTN_SMEM_BYTES);

    dim3 gqkv(SEQ / 64, 3);
    qkv_kernel<<<gqkv, 256>>>(X, Wq, Wk, Wv);

    dim3 gattn(SEQ / BM, NSPLIT);
    attn_kernel<<<gattn, 256, ATTN_SMEM_BYTES>>>();

    merge_kernel<<<SEQ * D / 256, 256>>>(out);
}

// round 9
// speedup vs baseline: 2.9029x; 2.0008x over previous
#include <cuda_runtime.h>
#include <cstdint>

#define SEQ 8192
#define DIM 512
#define D   64
#define BM  128
#define BN  64
#define NSPLIT 2
#define NITER (SEQ / NSPLIT / BN)   // 64

// ---------------- device scratch (no allocations allowed) -------------------
__device__ float g_Q  [SEQ * D];        // fp32 row-major, scaled by 0.125*log2(e)
__device__ float g_KhI[SEQ * D];        // tf32(K) hi, B-frag interleaved layout
__device__ float g_KlI[SEQ * D];        // tf32(K - Kh), same layout
__device__ float g_VI [SEQ * D];        // tf32(V), PV B-frag interleaved layout
__device__ float g_Op[NSPLIT][SEQ * D]; // unnormalized partial O
__device__ float g_ms[NSPLIT][SEQ];     // row max (log2 units)
__device__ float g_ls[NSPLIT][SEQ];     // row sum

using u64 = unsigned long long;

// ---------------- PTX helpers ----------------------------------------------
__device__ __forceinline__ uint32_t smem_u32(const void* p) {
    uint32_t a;
    asm("{ .reg .u64 t; cvta.to.shared.u64 t, %1; cvt.u32.u64 %0, t; }" : "=r"(a) : "l"(p));
    return a;
}
__device__ __forceinline__ float tf32r(float x) {
    uint32_t u; asm("cvt.rna.tf32.f32 %0, %1;" : "=r"(u) : "f"(x));
    return __uint_as_float(u);
}
__device__ __forceinline__ float ex2(float x) {
    float y; asm("ex2.approx.f32 %0, %1;" : "=f"(y) : "f"(x)); return y;
}
__device__ __forceinline__ void cp_async16(uint32_t dst, const void* src) {
    asm volatile("cp.async.cg.shared.global [%0], [%1], 16;" :: "r"(dst), "l"(src) : "memory");
}
#define CP_COMMIT() asm volatile("cp.async.commit_group;" ::: "memory")
#define CP_WAIT0()  asm volatile("cp.async.wait_group 0;" ::: "memory")

// m16n8k8 tf32 mma: D = A*B + D   (A: 4 b32 regs, B: 2 b32 regs, D: 4 f32)
__device__ __forceinline__ void mma8(float* d, const uint32_t* a, uint32_t b0, uint32_t b1) {
    asm volatile(
        "mma.sync.aligned.m16n8k8.row.col.f32.tf32.tf32.f32 "
        "{%0,%1,%2,%3}, {%4,%5,%6,%7}, {%8,%9}, {%0,%1,%2,%3};"
        : "+f"(d[0]), "+f"(d[1]), "+f"(d[2]), "+f"(d[3])
        : "r"(a[0]), "r"(a[1]), "r"(a[2]), "r"(a[3]), "r"(b0), "r"(b1));
}

// ---- packed f32x2 helpers (qkv kernel) ----
__device__ __forceinline__ u64 pack2(float lo, float hi) {
    u64 r; asm("mov.b64 %0, {%1, %2};" : "=l"(r) : "f"(lo), "f"(hi)); return r;
}
__device__ __forceinline__ u64 dup2(float v) { return pack2(v, v); }
__device__ __forceinline__ u64 ffma2(u64 a, u64 b, u64 c) {
    u64 d; asm("fma.rn.f32x2 %0, %1, %2, %3;" : "=l"(d) : "l"(a), "l"(b), "l"(c)); return d;
}
__device__ __forceinline__ float2 unpack2(u64 v) {
    float lo, hi; asm("mov.b64 {%0, %1}, %2;" : "=f"(lo), "=f"(hi) : "l"(v));
    return make_float2(lo, hi);
}

// ============================================================================
// QKV projection (fp32 FFMA2).
// grid.y: 0 -> g_Q (scaled by 0.125*log2e), 1 -> g_KhI/g_KlI, 2 -> g_VI.
// K frag layout:  idx = ((d>>3)*SEQ + key)*8 + (d&3)*2 + ((d>>2)&1)
// V frag layout:  idx = (key>>3)*512 + d*8 + (key&3)*2 + ((key>>2)&1)
// ============================================================================
__global__ __launch_bounds__(256) void qkv_kernel(
    const float* __restrict__ X, const float* __restrict__ Wq,
    const float* __restrict__ Wk, const float* __restrict__ Wv)
{
    __shared__ float sX[32 * 68];
    __shared__ float sW[32 * 68];

    const int m = blockIdx.y;
    const float* __restrict__ W = (m == 0) ? Wq : (m == 1) ? Wk : Wv;
    const int row0 = blockIdx.x * 64;
    const int tid = threadIdx.x;
    const int tx = tid & 15, ty = tid >> 4;

    u64 acc[4][2];
    #pragma unroll
    for (int r = 0; r < 4; r++) { acc[r][0] = 0ull; acc[r][1] = 0ull; }

    for (int k0 = 0; k0 < DIM; k0 += 32) {
        #pragma unroll
        for (int i = tid; i < 64 * 32; i += 256) {
            int r = i >> 5, k = i & 31;
            sX[k * 68 + r] = X[(row0 + r) * DIM + k0 + k];
        }
        #pragma unroll
        for (int i = tid; i < 32 * 64; i += 256) {
            int k = i >> 6, c = i & 63;
            sW[k * 68 + c] = W[(k0 + k) * D + c];
        }
        __syncthreads();
        #pragma unroll 8
        for (int k = 0; k < 32; k++) {
            float4 a4 = *reinterpret_cast<const float4*>(&sX[k * 68 + ty * 4]);
            ulonglong2 b = *reinterpret_cast<const ulonglong2*>(&sW[k * 68 + tx * 4]);
            u64 A0 = dup2(a4.x), A1 = dup2(a4.y), A2 = dup2(a4.z), A3 = dup2(a4.w);
            acc[0][0] = ffma2(A0, b.x, acc[0][0]); acc[0][1] = ffma2(A0, b.y, acc[0][1]);
            acc[1][0] = ffma2(A1, b.x, acc[1][0]); acc[1][1] = ffma2(A1, b.y, acc[1][1]);
            acc[2][0] = ffma2(A2, b.x, acc[2][0]); acc[2][1] = ffma2(A2, b.y, acc[2][1]);
            acc[3][0] = ffma2(A3, b.x, acc[3][0]); acc[3][1] = ffma2(A3, b.y, acc[3][1]);
        }
        __syncthreads();
    }

    float f[4][4];
    #pragma unroll
    for (int r = 0; r < 4; r++) {
        float2 c01 = unpack2(acc[r][0]);
        float2 c23 = unpack2(acc[r][1]);
        f[r][0] = c01.x; f[r][1] = c01.y; f[r][2] = c23.x; f[r][3] = c23.y;
    }

    if (m == 0) {
        const float qscale = 0.125f * 1.4426950408889634f;  // fold 1/sqrt(64) and log2(e)
        #pragma unroll
        for (int r = 0; r < 4; r++)
            *reinterpret_cast<float4*>(&g_Q[(row0 + ty * 4 + r) * D + tx * 4]) =
                make_float4(f[r][0] * qscale, f[r][1] * qscale,
                            f[r][2] * qscale, f[r][3] * qscale);
    } else if (m == 1) {
        #pragma unroll
        for (int r = 0; r < 4; r++) {
            int key = row0 + ty * 4 + r;
            #pragma unroll
            for (int cc = 0; cc < 4; cc++) {
                int d = tx * 4 + cc;
                float h = tf32r(f[r][cc]);
                float l = tf32r(f[r][cc] - h);
                int idx = ((d >> 3) * SEQ + key) * 8 + (d & 3) * 2 + ((d >> 2) & 1);
                g_KhI[idx] = h;
                g_KlI[idx] = l;
            }
        }
    } else {
        #pragma unroll
        for (int r = 0; r < 4; r++) {
            int key = row0 + ty * 4 + r;
            #pragma unroll
            for (int cc = 0; cc < 4; cc++) {
                int d = tx * 4 + cc;
                int idx = (key >> 3) * 512 + d * 8 + (key & 3) * 2 + ((key >> 2) & 1);
                g_VI[idx] = tf32r(f[r][cc]);
            }
        }
    }
}

// ============================================================================
// Flash attention via mma.sync tf32 (split precision).
// 8 warps x 16 rows = BM 128. BN=64 keys/iter, double-buffered cp.async.
// smem floats: [2][12288] KV buffers (Kh|Kl|V, 4096 floats each),
//              then per-warp P: [8][2][1088]  ([16][68] hi + lo).
// ============================================================================
#define KVBUF 12288
#define ATTN_SMEM_FLOATS (2 * KVBUF + 8 * 2 * 1088)
#define ATTN_SMEM_BYTES  (ATTN_SMEM_FLOATS * 4)   // 167936

__device__ __forceinline__ void load_tiles(float* smbuf, int n0, int tid) {
    uint32_t sb = smem_u32(smbuf);
    const char* khp = (const char*)g_KhI;
    const char* klp = (const char*)g_KlI;
    const char* vp  = (const char*)g_VI;
    #pragma unroll
    for (int j = 0; j < 4; j++) {
        int c = tid + 256 * j;          // 0..1023 chunk id (16B chunks)
        int g = c >> 7, cw = c & 127;
        size_t go = ((size_t)(g * SEQ + n0)) * 32 + (size_t)cw * 16;
        cp_async16(sb + c * 16,         khp + go);
        cp_async16(sb + 16384 + c * 16, klp + go);
        cp_async16(sb + 32768 + c * 16, vp + (size_t)n0 * 256 + (size_t)c * 16);
    }
}

__global__ __launch_bounds__(256, 1) void attn_kernel()
{
    extern __shared__ float sm[];
    float* bufs = sm;                 // [2][KVBUF]
    const int tid  = threadIdx.x;
    const int warp = tid >> 5;
    const int lane = tid & 31;
    const int gid  = lane >> 2;       // 0..7
    const int tig  = lane & 3;        // 0..3
    const int q0 = blockIdx.x * BM;
    const int split = blockIdx.y;
    const int n_begin = split * (SEQ / NSPLIT);

    float* ph = sm + 2 * KVBUF + warp * 2176;
    float* pl = ph + 1088;

    // ---- Q fragments (loop-invariant, registers) ----
    uint32_t qh[8][4], ql[8][4];
    {
        const float* qa = &g_Q[(q0 + warp * 16 + gid) * D];
        const float* qb = qa + 8 * D;
        #pragma unroll
        for (int g = 0; g < 8; g++) {
            float v0 = qa[8 * g + tig],     v2 = qa[8 * g + tig + 4];
            float v1 = qb[8 * g + tig],     v3 = qb[8 * g + tig + 4];
            float h;
            h = tf32r(v0); qh[g][0] = __float_as_uint(h); ql[g][0] = __float_as_uint(tf32r(v0 - h));
            h = tf32r(v1); qh[g][1] = __float_as_uint(h); ql[g][1] = __float_as_uint(tf32r(v1 - h));
            h = tf32r(v2); qh[g][2] = __float_as_uint(h); ql[g][2] = __float_as_uint(tf32r(v2 - h));
            h = tf32r(v3); qh[g][3] = __float_as_uint(h); ql[g][3] = __float_as_uint(tf32r(v3 - h));
        }
    }

    float oacc[8][4];
    #pragma unroll
    for (int nt = 0; nt < 8; nt++)
        #pragma unroll
        for (int c = 0; c < 4; c++) oacc[nt][c] = 0.0f;
    float mA = -INFINITY, mB = -INFINITY, lA = 0.0f, lB = 0.0f;

    load_tiles(bufs, n_begin, tid);
    CP_COMMIT();

    const int koff = gid * 8 + tig * 2;   // per-thread invariant frag offset (floats)

    for (int i = 0; i < NITER; i++) {
        const int b = i & 1;
        float* kb = bufs + b * KVBUF;
        CP_WAIT0();
        __syncthreads();
        if (i + 1 < NITER)
            load_tiles(bufs + (b ^ 1) * KVBUF, n_begin + (i + 1) * BN, tid);
        CP_COMMIT();

        // ---- S = Qh*Kh + Qh*Kl + Ql*Kh ----
        float sacc[8][4];
        #pragma unroll
        for (int nt = 0; nt < 8; nt++)
            #pragma unroll
            for (int c = 0; c < 4; c++) sacc[nt][c] = 0.0f;

        const float* kh = kb;
        const float* kl = kb + 4096;
        #pragma unroll
        for (int g = 0; g < 8; g++) {
            #pragma unroll
            for (int nt = 0; nt < 8; nt++) {
                float2 bh = *reinterpret_cast<const float2*>(&kh[g * 512 + nt * 64 + koff]);
                float2 bl = *reinterpret_cast<const float2*>(&kl[g * 512 + nt * 64 + koff]);
                uint32_t bh0 = __float_as_uint(bh.x), bh1 = __float_as_uint(bh.y);
                uint32_t bl0 = __float_as_uint(bl.x), bl1 = __float_as_uint(bl.y);
                mma8(sacc[nt], qh[g], bh0, bh1);
                mma8(sacc[nt], qh[g], bl0, bl1);
                mma8(sacc[nt], ql[g], bh0, bh1);
            }
        }

        // ---- online softmax (rows rA=gid, rB=gid+8 within warp tile) ----
        float mxA = -INFINITY, mxB = -INFINITY;
        #pragma unroll
        for (int nt = 0; nt < 8; nt++) {
            mxA = fmaxf(mxA, fmaxf(sacc[nt][0], sacc[nt][1]));
            mxB = fmaxf(mxB, fmaxf(sacc[nt][2], sacc[nt][3]));
        }
        mxA = fmaxf(mxA, __shfl_xor_sync(0xffffffffu, mxA, 1));
        mxA = fmaxf(mxA, __shfl_xor_sync(0xffffffffu, mxA, 2));
        mxB = fmaxf(mxB, __shfl_xor_sync(0xffffffffu, mxB, 1));
        mxB = fmaxf(mxB, __shfl_xor_sync(0xffffffffu, mxB, 2));
        float mnA = fmaxf(mA, mxA), mnB = fmaxf(mB, mxB);
        float alA = ex2(mA - mnA),  alB = ex2(mB - mnB);
        mA = mnA; mB = mnB;

        #pragma unroll
        for (int nt = 0; nt < 8; nt++) {
            oacc[nt][0] *= alA; oacc[nt][1] *= alA;
            oacc[nt][2] *= alB; oacc[nt][3] *= alB;
        }

        float sumA = 0.0f, sumB = 0.0f;
        #pragma unroll
        for (int nt = 0; nt < 8; nt++) {
            float p0 = ex2(sacc[nt][0] - mnA);
            float p1 = ex2(sacc[nt][1] - mnA);
            float p2 = ex2(sacc[nt][2] - mnB);
            float p3 = ex2(sacc[nt][3] - mnB);
            sumA += p0 + p1; sumB += p2 + p3;
            float h0 = tf32r(p0), h1 = tf32r(p1), h2 = tf32r(p2), h3 = tf32r(p3);
            int baseA = gid * 68 + nt * 8 + 2 * tig;
            int baseB = (gid + 8) * 68 + nt * 8 + 2 * tig;
            *reinterpret_cast<float2*>(&ph[baseA]) = make_float2(h0, h1);
            *reinterpret_cast<float2*>(&ph[baseB]) = make_float2(h2, h3);
            *reinterpret_cast<float2*>(&pl[baseA]) = make_float2(tf32r(p0 - h0), tf32r(p1 - h1));
            *reinterpret_cast<float2*>(&pl[baseB]) = make_float2(tf32r(p2 - h2), tf32r(p3 - h3));
        }
        sumA += __shfl_xor_sync(0xffffffffu, sumA, 1);
        sumA += __shfl_xor_sync(0xffffffffu, sumA, 2);
        sumB += __shfl_xor_sync(0xffffffffu, sumB, 1);
        sumB += __shfl_xor_sync(0xffffffffu, sumB, 2);
        lA = lA * alA + sumA;
        lB = lB * alB + sumB;
        __syncwarp();   // P visible to all lanes of this warp

        // ---- O += (Ph + Pl) * V ----
        const float* vv = kb + 8192;
        #pragma unroll
        for (int gk = 0; gk < 8; gk++) {
            uint32_t ah[4], al4[4];
            int pa = gid * 68 + gk * 8 + tig;
            int pb = (gid + 8) * 68 + gk * 8 + tig;
            ah[0]  = __float_as_uint(ph[pa]);
            ah[1]  = __float_as_uint(ph[pb]);
            ah[2]  = __float_as_uint(ph[pa + 4]);
            ah[3]  = __float_as_uint(ph[pb + 4]);
            al4[0] = __float_as_uint(pl[pa]);
            al4[1] = __float_as_uint(pl[pb]);
            al4[2] = __float_as_uint(pl[pa + 4]);
            al4[3] = __float_as_uint(pl[pb + 4]);
            #pragma unroll
            for (int nt = 0; nt < 8; nt++) {
                float2 bv = *reinterpret_cast<const float2*>(&vv[gk * 512 + nt * 64 + koff]);
                uint32_t b0 = __float_as_uint(bv.x), b1 = __float_as_uint(bv.y);
                mma8(oacc[nt], ah, b0, b1);
                mma8(oacc[nt], al4, b0, b1);
            }
        }
        __syncwarp();   // P reads done before next iter overwrites
    }

    // ---- epilogue: unnormalized partials + stats ----
    int rowA = q0 + warp * 16 + gid;
    int rowB = rowA + 8;
    #pragma unroll
    for (int nt = 0; nt < 8; nt++) {
        *reinterpret_cast<float2*>(&g_Op[split][rowA * D + nt * 8 + 2 * tig]) =
            make_float2(oacc[nt][0], oacc[nt][1]);
        *reinterpret_cast<float2*>(&g_Op[split][rowB * D + nt * 8 + 2 * tig]) =
            make_float2(oacc[nt][2], oacc[nt][3]);
    }
    if (tig == 0) {
        g_ms[split][rowA] = mA; g_ls[split][rowA] = lA;
        g_ms[split][rowB] = mB; g_ls[split][rowB] = lB;
    }
}

// ============================================================================
// Merge the NSPLIT partials (stats in log2 units -> ex2).
// ============================================================================
__global__ __launch_bounds__(256) void merge_kernel(float* __restrict__ out)
{
    int idx = blockIdx.x * 256 + threadIdx.x;
    int row = idx >> 6;
    float m0 = g_ms[0][row], m1 = g_ms[1][row];
    float m = fmaxf(m0, m1);
    float e0 = ex2(m0 - m), e1 = ex2(m1 - m);
    float denom = e0 * g_ls[0][row] + e1 * g_ls[1][row];
    out[idx] = (e0 * g_Op[0][idx] + e1 * g_Op[1][idx]) / denom;
}

extern "C" void kernel_launch(void* const* d_in, const int* in_sizes, int n_in,
                              void* d_out, int out_size) {
    (void)in_sizes; (void)n_in; (void)out_size;
    const float* X  = (const float*)d_in[0];
    const float* Wq = (const float*)d_in[1];
    const float* Wk = (const float*)d_in[2];
    const float* Wv = (const float*)d_in[3];
    float* out = (float*)d_out;

    cudaFuncSetAttribute(attn_kernel,
                         cudaFuncAttributeMaxDynamicSharedMemorySize, ATTN_SMEM_BYTES);

    dim3 gqkv(SEQ / 64, 3);
    qkv_kernel<<<gqkv, 256>>>(X, Wq, Wk, Wv);

    dim3 gattn(SEQ / BM, NSPLIT);
    attn_kernel<<<gattn, 256, ATTN_SMEM_BYTES>>>();

    merge_kernel<<<SEQ * D / 256, 256>>>(out);
}

// round 10
// speedup vs baseline: 3.7128x; 1.2790x over previous
#include <cuda_runtime.h>
#include <cstdint>

#define SEQ 8192
#define DIM 512
#define D   64
#define BM  128
#define BN  64
#define NSPLIT 2
#define NITER (SEQ / NSPLIT / BN)   // 64

// ---------------- device scratch (no allocations allowed) -------------------
__device__ float    g_Q   [SEQ * D];      // fp32 row-major, scaled by 0.125*log2(e)
__device__ float    g_KhI [SEQ * D];      // tf32(K) hi, S B-frag interleaved layout
__device__ uint16_t g_KlB [SEQ * D];      // bf16(K - Kh), packed pairs (d, d+4)
__device__ float    g_VI  [SEQ * D];      // tf32(V), PV B-frag layout, plain key order
__device__ float g_Op[NSPLIT][SEQ * D];   // unnormalized partial O
__device__ float g_ms[NSPLIT][SEQ];       // row max (log2 units)
__device__ float g_ls[NSPLIT][SEQ];       // row sum

using u64 = unsigned long long;

// ---------------- PTX helpers ----------------------------------------------
__device__ __forceinline__ uint32_t smem_u32(const void* p) {
    uint32_t a;
    asm("{ .reg .u64 t; cvta.to.shared.u64 t, %1; cvt.u32.u64 %0, t; }" : "=r"(a) : "l"(p));
    return a;
}
__device__ __forceinline__ float tf32r(float x) {
    uint32_t u; asm("cvt.rna.tf32.f32 %0, %1;" : "=r"(u) : "f"(x));
    return __uint_as_float(u);
}
__device__ __forceinline__ float ex2(float x) {
    float y; asm("ex2.approx.f32 %0, %1;" : "=f"(y) : "f"(x)); return y;
}
__device__ __forceinline__ uint16_t bf16_rn(float x) {
    uint32_t u = __float_as_uint(x);
    uint32_t r = (u + 0x7FFFu + ((u >> 16) & 1u)) >> 16;   // round-to-nearest-even
    return (uint16_t)r;
}
__device__ __forceinline__ void cp_async16(uint32_t dst, const void* src) {
    asm volatile("cp.async.cg.shared.global [%0], [%1], 16;" :: "r"(dst), "l"(src) : "memory");
}
#define CP_COMMIT() asm volatile("cp.async.commit_group;" ::: "memory")
#define CP_WAIT0()  asm volatile("cp.async.wait_group 0;" ::: "memory")

// m16n8k8 tf32 mma: D = A*B + D
__device__ __forceinline__ void mma8(float* d, const uint32_t* a, uint32_t b0, uint32_t b1) {
    asm volatile(
        "mma.sync.aligned.m16n8k8.row.col.f32.tf32.tf32.f32 "
        "{%0,%1,%2,%3}, {%4,%5,%6,%7}, {%8,%9}, {%0,%1,%2,%3};"
        : "+f"(d[0]), "+f"(d[1]), "+f"(d[2]), "+f"(d[3])
        : "r"(a[0]), "r"(a[1]), "r"(a[2]), "r"(a[3]), "r"(b0), "r"(b1));
}

// ---- packed f32x2 helpers (qkv kernel) ----
__device__ __forceinline__ u64 pack2(float lo, float hi) {
    u64 r; asm("mov.b64 %0, {%1, %2};" : "=l"(r) : "f"(lo), "f"(hi)); return r;
}
__device__ __forceinline__ u64 dup2(float v) { return pack2(v, v); }
__device__ __forceinline__ u64 ffma2(u64 a, u64 b, u64 c) {
    u64 d; asm("fma.rn.f32x2 %0, %1, %2, %3;" : "=l"(d) : "l"(a), "l"(b), "l"(c)); return d;
}
__device__ __forceinline__ float2 unpack2(u64 v) {
    float lo, hi; asm("mov.b64 {%0, %1}, %2;" : "=f"(lo), "=f"(hi) : "l"(v));
    return make_float2(lo, hi);
}

// ============================================================================
// QKV projection (fp32 FFMA2).
// grid.y: 0 -> g_Q (scaled by 0.125*log2e)
//         1 -> g_KhI (tf32 hi, frag layout) + g_KlB (bf16 lo, packed pairs)
//         2 -> g_VI  (tf32, plain within-chunk key order)
// Kh frag layout: idx = ((d>>3)*SEQ + key)*8 + (d&3)*2 + ((d>>2)&1)
// Kl bf16 layout: u16 idx = (((d>>3)*SEQ + key)*4 + (d&3))*2 + ((d>>2)&1)
// V layout:       idx = (key>>3)*512 + d*8 + (key&7)
// ============================================================================
__global__ __launch_bounds__(256) void qkv_kernel(
    const float* __restrict__ X, const float* __restrict__ Wq,
    const float* __restrict__ Wk, const float* __restrict__ Wv)
{
    __shared__ float sX[32 * 68];
    __shared__ float sW[32 * 68];

    const int m = blockIdx.y;
    const float* __restrict__ W = (m == 0) ? Wq : (m == 1) ? Wk : Wv;
    const int row0 = blockIdx.x * 64;
    const int tid = threadIdx.x;
    const int tx = tid & 15, ty = tid >> 4;

    u64 acc[4][2];
    #pragma unroll
    for (int r = 0; r < 4; r++) { acc[r][0] = 0ull; acc[r][1] = 0ull; }

    for (int k0 = 0; k0 < DIM; k0 += 32) {
        #pragma unroll
        for (int i = tid; i < 64 * 32; i += 256) {
            int r = i >> 5, k = i & 31;
            sX[k * 68 + r] = X[(row0 + r) * DIM + k0 + k];
        }
        #pragma unroll
        for (int i = tid; i < 32 * 64; i += 256) {
            int k = i >> 6, c = i & 63;
            sW[k * 68 + c] = W[(k0 + k) * D + c];
        }
        __syncthreads();
        #pragma unroll 8
        for (int k = 0; k < 32; k++) {
            float4 a4 = *reinterpret_cast<const float4*>(&sX[k * 68 + ty * 4]);
            ulonglong2 b = *reinterpret_cast<const ulonglong2*>(&sW[k * 68 + tx * 4]);
            u64 A0 = dup2(a4.x), A1 = dup2(a4.y), A2 = dup2(a4.z), A3 = dup2(a4.w);
            acc[0][0] = ffma2(A0, b.x, acc[0][0]); acc[0][1] = ffma2(A0, b.y, acc[0][1]);
            acc[1][0] = ffma2(A1, b.x, acc[1][0]); acc[1][1] = ffma2(A1, b.y, acc[1][1]);
            acc[2][0] = ffma2(A2, b.x, acc[2][0]); acc[2][1] = ffma2(A2, b.y, acc[2][1]);
            acc[3][0] = ffma2(A3, b.x, acc[3][0]); acc[3][1] = ffma2(A3, b.y, acc[3][1]);
        }
        __syncthreads();
    }

    float f[4][4];
    #pragma unroll
    for (int r = 0; r < 4; r++) {
        float2 c01 = unpack2(acc[r][0]);
        float2 c23 = unpack2(acc[r][1]);
        f[r][0] = c01.x; f[r][1] = c01.y; f[r][2] = c23.x; f[r][3] = c23.y;
    }

    if (m == 0) {
        const float qscale = 0.125f * 1.4426950408889634f;
        #pragma unroll
        for (int r = 0; r < 4; r++)
            *reinterpret_cast<float4*>(&g_Q[(row0 + ty * 4 + r) * D + tx * 4]) =
                make_float4(f[r][0] * qscale, f[r][1] * qscale,
                            f[r][2] * qscale, f[r][3] * qscale);
    } else if (m == 1) {
        #pragma unroll
        for (int r = 0; r < 4; r++) {
            int key = row0 + ty * 4 + r;
            #pragma unroll
            for (int cc = 0; cc < 4; cc++) {
                int d = tx * 4 + cc;
                float h = tf32r(f[r][cc]);
                float l = f[r][cc] - h;
                int g = d >> 3;
                g_KhI[((g * SEQ + key) * 8) + (d & 3) * 2 + ((d >> 2) & 1)] = h;
                g_KlB[(((g * SEQ + key) * 4) + (d & 3)) * 2 + ((d >> 2) & 1)] = bf16_rn(l);
            }
        }
    } else {
        #pragma unroll
        for (int r = 0; r < 4; r++) {
            int key = row0 + ty * 4 + r;
            #pragma unroll
            for (int cc = 0; cc < 4; cc++) {
                int d = tx * 4 + cc;
                g_VI[(key >> 3) * 512 + d * 8 + (key & 7)] = tf32r(f[r][cc]);
            }
        }
    }
}

// ============================================================================
// Flash attention via mma.sync tf32. P never leaves registers:
// the V key-permuted layout makes the PV A-fragment identical to the S D-frag.
// smem per buffer: Kh 16KB | Kl(bf16) 8KB | V 16KB = 40KB, double buffered.
// ============================================================================
#define KVBUF_FLOATS 10240                 // 40960 bytes
#define ATTN_SMEM_BYTES (2 * KVBUF_FLOATS * 4)   // 81920

__device__ __forceinline__ void load_tiles(float* smbuf, int n0, int tid) {
    uint32_t sb = smem_u32(smbuf);
    const char* khp = (const char*)g_KhI;
    const char* klp = (const char*)g_KlB;
    const char* vp  = (const char*)g_VI;
    // Kh: 1024 x 16B chunks. Per g: 64 keys x 32B contiguous.
    #pragma unroll
    for (int j = 0; j < 4; j++) {
        int c = tid + 256 * j;
        int g = c >> 7, cw = c & 127;
        cp_async16(sb + c * 16, khp + ((size_t)(g * SEQ + n0)) * 32 + (size_t)cw * 16);
    }
    // Kl bf16: 512 x 16B chunks. Per g: 64 keys x 16B contiguous.
    #pragma unroll
    for (int j = 0; j < 2; j++) {
        int c = tid + 256 * j;
        int g = c >> 6, cw = c & 63;
        cp_async16(sb + 16384 + c * 16, klp + ((size_t)(g * SEQ + n0)) * 16 + (size_t)cw * 16);
    }
    // V: 1024 x 16B chunks, fully contiguous (256B per key).
    #pragma unroll
    for (int j = 0; j < 4; j++) {
        int c = tid + 256 * j;
        cp_async16(sb + 24576 + c * 16, vp + (size_t)n0 * 256 + (size_t)c * 16);
    }
}

__global__ __launch_bounds__(256, 1) void attn_kernel()
{
    extern __shared__ float sm[];
    float* bufs = sm;                 // [2][KVBUF_FLOATS]
    const int tid  = threadIdx.x;
    const int warp = tid >> 5;
    const int lane = tid & 31;
    const int gid  = lane >> 2;       // 0..7
    const int tig  = lane & 3;        // 0..3
    const int q0 = blockIdx.x * BM;
    const int split = blockIdx.y;
    const int n_begin = split * (SEQ / NSPLIT);

    // ---- Q fragments (loop-invariant, registers) ----
    uint32_t qh[8][4], ql[8][4];
    {
        const float* qa = &g_Q[(q0 + warp * 16 + gid) * D];
        const float* qb = qa + 8 * D;
        #pragma unroll
        for (int g = 0; g < 8; g++) {
            float v0 = qa[8 * g + tig],     v2 = qa[8 * g + tig + 4];
            float v1 = qb[8 * g + tig],     v3 = qb[8 * g + tig + 4];
            float h;
            h = tf32r(v0); qh[g][0] = __float_as_uint(h); ql[g][0] = __float_as_uint(tf32r(v0 - h));
            h = tf32r(v1); qh[g][1] = __float_as_uint(h); ql[g][1] = __float_as_uint(tf32r(v1 - h));
            h = tf32r(v2); qh[g][2] = __float_as_uint(h); ql[g][2] = __float_as_uint(tf32r(v2 - h));
            h = tf32r(v3); qh[g][3] = __float_as_uint(h); ql[g][3] = __float_as_uint(tf32r(v3 - h));
        }
    }

    float oacc[8][4];
    #pragma unroll
    for (int nt = 0; nt < 8; nt++)
        #pragma unroll
        for (int c = 0; c < 4; c++) oacc[nt][c] = 0.0f;
    float mA = -INFINITY, mB = -INFINITY, lA = 0.0f, lB = 0.0f;

    load_tiles(bufs, n_begin, tid);
    CP_COMMIT();

    const int koff = gid * 8 + tig * 2;

    for (int i = 0; i < NITER; i++) {
        const int b = i & 1;
        float* kb = bufs + b * KVBUF_FLOATS;
        CP_WAIT0();
        __syncthreads();
        if (i + 1 < NITER)
            load_tiles(bufs + (b ^ 1) * KVBUF_FLOATS, n_begin + (i + 1) * BN, tid);
        CP_COMMIT();

        // ---- S = Qh*Kh + Ql*Kh + Qh*Kl ----
        float sacc[8][4];
        #pragma unroll
        for (int nt = 0; nt < 8; nt++)
            #pragma unroll
            for (int c = 0; c < 4; c++) sacc[nt][c] = 0.0f;

        const float* kh = kb;
        const uint32_t* klb = reinterpret_cast<const uint32_t*>(kb + 4096);
        #pragma unroll
        for (int g = 0; g < 8; g++) {
            #pragma unroll
            for (int nt = 0; nt < 8; nt++) {
                float2 bh = *reinterpret_cast<const float2*>(&kh[g * 512 + nt * 64 + koff]);
                uint32_t kk = klb[g * 256 + (nt * 8 + gid) * 4 + tig];
                uint32_t bh0 = __float_as_uint(bh.x), bh1 = __float_as_uint(bh.y);
                uint32_t bl0 = kk << 16, bl1 = kk & 0xFFFF0000u;
                mma8(sacc[nt], qh[g], bh0, bh1);
                mma8(sacc[nt], ql[g], bh0, bh1);
                mma8(sacc[nt], qh[g], bl0, bl1);
            }
        }

        // ---- online softmax; P (tf32-rounded) kept in registers ----
        float mxA = -INFINITY, mxB = -INFINITY;
        #pragma unroll
        for (int nt = 0; nt < 8; nt++) {
            mxA = fmaxf(mxA, fmaxf(sacc[nt][0], sacc[nt][1]));
            mxB = fmaxf(mxB, fmaxf(sacc[nt][2], sacc[nt][3]));
        }
        mxA = fmaxf(mxA, __shfl_xor_sync(0xffffffffu, mxA, 1));
        mxA = fmaxf(mxA, __shfl_xor_sync(0xffffffffu, mxA, 2));
        mxB = fmaxf(mxB, __shfl_xor_sync(0xffffffffu, mxB, 1));
        mxB = fmaxf(mxB, __shfl_xor_sync(0xffffffffu, mxB, 2));
        float mnA = fmaxf(mA, mxA), mnB = fmaxf(mB, mxB);
        float alA = ex2(mA - mnA),  alB = ex2(mB - mnB);
        mA = mnA; mB = mnB;

        uint32_t pf[8][4];
        float sumA = 0.0f, sumB = 0.0f;
        #pragma unroll
        for (int nt = 0; nt < 8; nt++) {
            float p0 = tf32r(ex2(sacc[nt][0] - mnA));
            float p1 = tf32r(ex2(sacc[nt][1] - mnA));
            float p2 = tf32r(ex2(sacc[nt][2] - mnB));
            float p3 = tf32r(ex2(sacc[nt][3] - mnB));
            sumA += p0 + p1; sumB += p2 + p3;
            // A-frag order: a0=(gid,k=tig)->c0, a1=(gid+8,k=tig)->c2,
            //               a2=(gid,k=tig+4)->c1, a3=(gid+8,k=tig+4)->c3
            pf[nt][0] = __float_as_uint(p0);
            pf[nt][1] = __float_as_uint(p2);
            pf[nt][2] = __float_as_uint(p1);
            pf[nt][3] = __float_as_uint(p3);
        }
        sumA += __shfl_xor_sync(0xffffffffu, sumA, 1);
        sumA += __shfl_xor_sync(0xffffffffu, sumA, 2);
        sumB += __shfl_xor_sync(0xffffffffu, sumB, 1);
        sumB += __shfl_xor_sync(0xffffffffu, sumB, 2);
        lA = lA * alA + sumA;
        lB = lB * alB + sumB;

        #pragma unroll
        for (int nt = 0; nt < 8; nt++) {
            oacc[nt][0] *= alA; oacc[nt][1] *= alA;
            oacc[nt][2] *= alB; oacc[nt][3] *= alB;
        }

        // ---- O += P * V (A-frag = registers, B from permuted V tile) ----
        const float* vv = kb + 6144;
        #pragma unroll
        for (int gk = 0; gk < 8; gk++) {
            #pragma unroll
            for (int nt = 0; nt < 8; nt++) {
                float2 bv = *reinterpret_cast<const float2*>(&vv[gk * 512 + nt * 64 + koff]);
                mma8(oacc[nt], pf[gk], __float_as_uint(bv.x), __float_as_uint(bv.y));
            }
        }
    }

    // ---- epilogue: unnormalized partials + stats ----
    int rowA = q0 + warp * 16 + gid;
    int rowB = rowA + 8;
    #pragma unroll
    for (int nt = 0; nt < 8; nt++) {
        *reinterpret_cast<float2*>(&g_Op[split][rowA * D + nt * 8 + 2 * tig]) =
            make_float2(oacc[nt][0], oacc[nt][1]);
        *reinterpret_cast<float2*>(&g_Op[split][rowB * D + nt * 8 + 2 * tig]) =
            make_float2(oacc[nt][2], oacc[nt][3]);
    }
    if (tig == 0) {
        g_ms[split][rowA] = mA; g_ls[split][rowA] = lA;
        g_ms[split][rowB] = mB; g_ls[split][rowB] = lB;
    }
}

// ============================================================================
// Merge the NSPLIT partials (stats in log2 units -> ex2).
// ============================================================================
__global__ __launch_bounds__(256) void merge_kernel(float* __restrict__ out)
{
    int idx = blockIdx.x * 256 + threadIdx.x;
    int row = idx >> 6;
    float m0 = g_ms[0][row], m1 = g_ms[1][row];
    float m = fmaxf(m0, m1);
    float e0 = ex2(m0 - m), e1 = ex2(m1 - m);
    float denom = e0 * g_ls[0][row] + e1 * g_ls[1][row];
    out[idx] = (e0 * g_Op[0][idx] + e1 * g_Op[1][idx]) / denom;
}

extern "C" void kernel_launch(void* const* d_in, const int* in_sizes, int n_in,
                              void* d_out, int out_size) {
    (void)in_sizes; (void)n_in; (void)out_size;
    const float* X  = (const float*)d_in[0];
    const float* Wq = (const float*)d_in[1];
    const float* Wk = (const float*)d_in[2];
    const float* Wv = (const float*)d_in[3];
    float* out = (float*)d_out;

    cudaFuncSetAttribute(attn_kernel,
                         cudaFuncAttributeMaxDynamicSharedMemorySize, ATTN_SMEM_BYTES);

    dim3 gqkv(SEQ / 64, 3);
    qkv_kernel<<<gqkv, 256>>>(X, Wq, Wk, Wv);

    dim3 gattn(SEQ / BM, NSPLIT);
    attn_kernel<<<gattn, 256, ATTN_SMEM_BYTES>>>();

    merge_kernel<<<SEQ * D / 256, 256>>>(out);
}